// round 14
// baseline (speedup 1.0000x reference)
#include <cuda_runtime.h>
#include <math.h>

// Problem shape (fixed by the benchmark):
// video [B=8, C=1024, T=64, W=14, H=14] fp32
// params mu_x, mu_y, sigma_x, sigma_y: [N=3] fp32
// out [B, C*N] = einsum('bctwh,nwh->bcn', video, filters) / T
#define N_FILT 3
#define W_DIM 14
#define H_DIM 14
#define WH 196              // W*H
#define WH4 49              // WH/4
#define T_DIM 64
#define T_GROUPS 5          // time-slices per CTA thread-group
#define ACTIVE_THREADS (WH4 * T_GROUPS)  // 245
#define SLAB (T_DIM * WH)   // 12544 floats per (b,c)
#define SLAB4 (SLAB / 4)    // 3136 float4 per (b,c)

// Filters pre-scaled by 1/(sum+eps) * (1/T), stored as float4 for vector LDG.
__device__ float4 g_filt4[N_FILT * WH4];

// Fast tanh via MUFU exp: 1 - 2/(e^{2x}+1). Rel err ~1e-6.
__device__ __forceinline__ float fast_tanh(float x) {
    float t = __expf(2.0f * x);
    return 1.0f - 2.0f / (t + 1.0f);
}
__device__ __forceinline__ float fast_sigmoid(float x) {
    return 1.0f / (1.0f + __expf(-x));
}

// ---------------------------------------------------------------------------
// Pre-kernel: 3 blocks, one per filter, MUFU-based. Paid once chip-wide.
// ---------------------------------------------------------------------------
__global__ void filter_kernel(const float* __restrict__ mu_x,
                              const float* __restrict__ mu_y,
                              const float* __restrict__ sigma_x,
                              const float* __restrict__ sigma_y) {
    const int n = blockIdx.x;
    const int tid = threadIdx.x;
    __shared__ float red[7];

    float mx = fast_tanh(mu_x[n]);
    float my = fast_tanh(mu_y[n]);
    float sx = __expf(1.5f - 2.0f * fast_sigmoid(sigma_x[n]));
    float sy = __expf(1.5f - 2.0f * fast_sigmoid(sigma_y[n]));
    float inv_x = 1.0f / (sx * sx + 1e-6f);
    float inv_y = 1.0f / (sy * sy + 1e-6f);
    float mux = (float)(W_DIM - 1) * ((mx + 1.0f) * 0.5f);
    float muy = (float)(H_DIM - 1) * ((my + 1.0f) * 0.5f);

    float v = 0.0f;
    if (tid < WH) {
        int w = tid / H_DIM;
        int h = tid - w * H_DIM;
        float dx = (float)w - mux;
        float dy = (float)h - muy;
        v = __expf(-0.5f * (dx * dx * inv_x + dy * dy * inv_y));
    }
    float s = v;
    #pragma unroll
    for (int off = 16; off > 0; off >>= 1)
        s += __shfl_xor_sync(0xFFFFFFFFu, s, off);
    if ((tid & 31) == 0) red[tid >> 5] = s;
    __syncthreads();
    float tot = 0.0f;
    #pragma unroll
    for (int w = 0; w < 7; w++) tot += red[w];
    float scale = 1.0f / ((tot + 1e-6f) * (float)T_DIM);
    if (tid < WH) {
        ((float*)g_filt4)[n * WH + tid] = v * scale;
    }
}

// ---------------------------------------------------------------------------
// Main kernel — the FASTEST measured pool variant (Round-2 configuration,
// pool=63.9us, DRAM=81.9%): occupancy 5 (48-reg budget lets ptxas front-batch
// 4 loads per unrolled group, MLP_p1=4), plain `for (t=g; t<T; t+=5)` loop
// with #pragma unroll 4, __ldg. Thread owns one spatial float4 position p,
// its 3 filter float4s live in registers. Inner: 1 LDG.128 + 12 FFMA.
// PDL sync at entry overlaps this kernel's launch with filter_kernel.
// ---------------------------------------------------------------------------
__global__ __launch_bounds__(256, 5)
void pool_kernel(const float* __restrict__ video, float* __restrict__ out) {
    const int bc = blockIdx.x;
    const int tid = threadIdx.x;

#if __CUDA_ARCH__ >= 900
    cudaGridDependencySynchronize();
#endif

    float a0 = 0.0f, a1 = 0.0f, a2 = 0.0f;

    if (tid < ACTIVE_THREADS) {
        const int g = tid / WH4;        // time-group 0..4
        const int p = tid - g * WH4;    // spatial float4 position 0..48

        const float4 f0 = g_filt4[p];
        const float4 f1 = g_filt4[WH4 + p];
        const float4 f2 = g_filt4[2 * WH4 + p];

        const float4* vp = (const float4*)video + (size_t)bc * SLAB4 + p;

        #pragma unroll 4
        for (int t = g; t < T_DIM; t += T_GROUPS) {
            float4 v = __ldg(&vp[t * WH4]);
            a0 += v.x * f0.x + v.y * f0.y + v.z * f0.z + v.w * f0.w;
            a1 += v.x * f1.x + v.y * f1.y + v.z * f1.z + v.w * f1.w;
            a2 += v.x * f2.x + v.y * f2.y + v.z * f2.z + v.w * f2.w;
        }
    }

    // warp reduction (all 256 threads participate; inactive ones carry zeros)
    #pragma unroll
    for (int off = 16; off > 0; off >>= 1) {
        a0 += __shfl_xor_sync(0xFFFFFFFFu, a0, off);
        a1 += __shfl_xor_sync(0xFFFFFFFFu, a1, off);
        a2 += __shfl_xor_sync(0xFFFFFFFFu, a2, off);
    }

    __shared__ float part[8][N_FILT];
    const int wid = tid >> 5;
    const int lid = tid & 31;
    if (lid == 0) {
        part[wid][0] = a0;
        part[wid][1] = a1;
        part[wid][2] = a2;
    }
    __syncthreads();

    if (tid < N_FILT) {
        float s = 0.0f;
        #pragma unroll
        for (int w = 0; w < 8; w++) s += part[w][tid];
        out[(size_t)bc * N_FILT + tid] = s;
    }
}

// ---------------------------------------------------------------------------
extern "C" void kernel_launch(void* const* d_in, const int* in_sizes, int n_in,
                              void* d_out, int out_size) {
    const float* video   = (const float*)d_in[0];
    const float* mu_x    = (const float*)d_in[1];
    const float* mu_y    = (const float*)d_in[2];
    const float* sigma_x = (const float*)d_in[3];
    const float* sigma_y = (const float*)d_in[4];
    float* out = (float*)d_out;

    const int n_bc = in_sizes[0] / SLAB;  // B*C = 8192

    filter_kernel<<<N_FILT, 224>>>(mu_x, mu_y, sigma_x, sigma_y);

    // Pool launched with programmatic dependent launch: it may begin while
    // filter_kernel is still running; cudaGridDependencySynchronize() inside
    // pool_kernel guarantees g_filt4 visibility before it is read.
    cudaLaunchConfig_t cfg = {};
    cfg.gridDim = dim3((unsigned)n_bc, 1, 1);
    cfg.blockDim = dim3(256, 1, 1);
    cfg.dynamicSmemBytes = 0;
    cfg.stream = 0;
    cudaLaunchAttribute attrs[1];
    attrs[0].id = cudaLaunchAttributeProgrammaticStreamSerialization;
    attrs[0].val.programmaticStreamSerializationAllowed = 1;
    cfg.attrs = attrs;
    cfg.numAttrs = 1;
    cudaLaunchKernelEx(&cfg, pool_kernel, (const float*)video, out);
}

// round 15
// speedup vs baseline: 1.0201x; 1.0201x over previous
#include <cuda_runtime.h>
#include <math.h>

// Problem shape (fixed by the benchmark):
// video [B=8, C=1024, T=64, W=14, H=14] fp32
// params mu_x, mu_y, sigma_x, sigma_y: [N=3] fp32
// out [B, C*N] = einsum('bctwh,nwh->bcn', video, filters) / T
//
// FINAL (converged after 14 ncu-driven rounds):
//  - pool_kernel is HBM-bound: all sane hot-loop variants land at
//    64.4-65.7us / 79.7-81.9% DRAM => ~6.4 TB/s is this read-stream's
//    effective ceiling on sm_103a (LTS-cap path-independent; TMA won't beat it).
//  - Hot loop: 1 LDG.128 + 12 FFMA, filters register-resident, plain unroll-2
//    (ptxas front-batches loads; hand-pipelining, __ldcs, slab-pairing,
//    persistent CTAs, and kernel fusion all measurably regress).
//  - 8 CTAs/SM (32 regs): 8192/(148*8)=6.92 waves, 92%-full last wave.
//  - Tiny MUFU filter pre-kernel (paid once chip-wide) + PDL overlap.
#define N_FILT 3
#define W_DIM 14
#define H_DIM 14
#define WH 196              // W*H
#define WH4 49              // WH/4
#define T_DIM 64
#define T_GROUPS 5          // time-slices per CTA thread-group
#define ACTIVE_THREADS (WH4 * T_GROUPS)  // 245
#define SLAB (T_DIM * WH)   // 12544 floats per (b,c)
#define SLAB4 (SLAB / 4)    // 3136 float4 per (b,c)

// Filters pre-scaled by 1/(sum+eps) * (1/T), stored as float4 for vector LDG.
__device__ float4 g_filt4[N_FILT * WH4];

// Fast tanh via MUFU exp: 1 - 2/(e^{2x}+1). Rel err ~1e-6.
__device__ __forceinline__ float fast_tanh(float x) {
    float t = __expf(2.0f * x);
    return 1.0f - 2.0f / (t + 1.0f);
}
__device__ __forceinline__ float fast_sigmoid(float x) {
    return 1.0f / (1.0f + __expf(-x));
}

// ---------------------------------------------------------------------------
// Pre-kernel: 3 blocks, one per filter, MUFU-based. Paid once chip-wide.
// ---------------------------------------------------------------------------
__global__ void filter_kernel(const float* __restrict__ mu_x,
                              const float* __restrict__ mu_y,
                              const float* __restrict__ sigma_x,
                              const float* __restrict__ sigma_y) {
    const int n = blockIdx.x;
    const int tid = threadIdx.x;
    __shared__ float red[7];

    float mx = fast_tanh(mu_x[n]);
    float my = fast_tanh(mu_y[n]);
    float sx = __expf(1.5f - 2.0f * fast_sigmoid(sigma_x[n]));
    float sy = __expf(1.5f - 2.0f * fast_sigmoid(sigma_y[n]));
    float inv_x = 1.0f / (sx * sx + 1e-6f);
    float inv_y = 1.0f / (sy * sy + 1e-6f);
    float mux = (float)(W_DIM - 1) * ((mx + 1.0f) * 0.5f);
    float muy = (float)(H_DIM - 1) * ((my + 1.0f) * 0.5f);

    float v = 0.0f;
    if (tid < WH) {
        int w = tid / H_DIM;
        int h = tid - w * H_DIM;
        float dx = (float)w - mux;
        float dy = (float)h - muy;
        v = __expf(-0.5f * (dx * dx * inv_x + dy * dy * inv_y));
    }
    float s = v;
    #pragma unroll
    for (int off = 16; off > 0; off >>= 1)
        s += __shfl_xor_sync(0xFFFFFFFFu, s, off);
    if ((tid & 31) == 0) red[tid >> 5] = s;
    __syncthreads();
    float tot = 0.0f;
    #pragma unroll
    for (int w = 0; w < 7; w++) tot += red[w];
    float scale = 1.0f / ((tot + 1e-6f) * (float)T_DIM);
    if (tid < WH) {
        ((float*)g_filt4)[n * WH + tid] = v * scale;
    }
}

// ---------------------------------------------------------------------------
// Main kernel: one CTA per (b,c) slab; thread owns one spatial float4
// position p (3 filter float4s in registers) and strides time t = g, g+5, ...
// ---------------------------------------------------------------------------
__global__ __launch_bounds__(256, 8)
void pool_kernel(const float4* __restrict__ video4, float* __restrict__ out) {
    const int bc = blockIdx.x;
    const int tid = threadIdx.x;

#if __CUDA_ARCH__ >= 900
    cudaGridDependencySynchronize();
#endif

    float a0 = 0.0f, a1 = 0.0f, a2 = 0.0f;

    if (tid < ACTIVE_THREADS) {
        const int g = tid / WH4;        // time-group 0..4
        const int p = tid - g * WH4;    // spatial float4 position 0..48

        const float4 f0 = g_filt4[p];
        const float4 f1 = g_filt4[WH4 + p];
        const float4 f2 = g_filt4[2 * WH4 + p];

        const float4* vp = video4 + bc * SLAB4 + g * WH4 + p;
        const int iters = (g == T_GROUPS - 1) ? 12 : 13;  // ceil((64-g)/5)

        #pragma unroll 2
        for (int it = 0; it < iters; it++) {
            float4 v = __ldg(vp);
            vp += T_GROUPS * WH4;
            a0 += v.x * f0.x + v.y * f0.y + v.z * f0.z + v.w * f0.w;
            a1 += v.x * f1.x + v.y * f1.y + v.z * f1.z + v.w * f1.w;
            a2 += v.x * f2.x + v.y * f2.y + v.z * f2.z + v.w * f2.w;
        }
    }

    // warp reduction (all 256 threads participate; inactive ones carry zeros)
    #pragma unroll
    for (int off = 16; off > 0; off >>= 1) {
        a0 += __shfl_xor_sync(0xFFFFFFFFu, a0, off);
        a1 += __shfl_xor_sync(0xFFFFFFFFu, a1, off);
        a2 += __shfl_xor_sync(0xFFFFFFFFu, a2, off);
    }

    __shared__ float part[8][N_FILT];
    const int wid = tid >> 5;
    const int lid = tid & 31;
    if (lid == 0) {
        part[wid][0] = a0;
        part[wid][1] = a1;
        part[wid][2] = a2;
    }
    __syncthreads();

    if (tid < N_FILT) {
        float s = 0.0f;
        #pragma unroll
        for (int w = 0; w < 8; w++) s += part[w][tid];
        out[bc * N_FILT + tid] = s;
    }
}

// ---------------------------------------------------------------------------
extern "C" void kernel_launch(void* const* d_in, const int* in_sizes, int n_in,
                              void* d_out, int out_size) {
    const float* video   = (const float*)d_in[0];
    const float* mu_x    = (const float*)d_in[1];
    const float* mu_y    = (const float*)d_in[2];
    const float* sigma_x = (const float*)d_in[3];
    const float* sigma_y = (const float*)d_in[4];
    float* out = (float*)d_out;

    const int n_bc = in_sizes[0] / SLAB;  // B*C = 8192

    filter_kernel<<<N_FILT, 224>>>(mu_x, mu_y, sigma_x, sigma_y);

    // Pool launched with programmatic dependent launch: it may begin while
    // filter_kernel is still running; cudaGridDependencySynchronize() inside
    // pool_kernel guarantees g_filt4 visibility before it is read.
    cudaLaunchConfig_t cfg = {};
    cfg.gridDim = dim3((unsigned)n_bc, 1, 1);
    cfg.blockDim = dim3(256, 1, 1);
    cfg.dynamicSmemBytes = 0;
    cfg.stream = 0;
    cudaLaunchAttribute attrs[1];
    attrs[0].id = cudaLaunchAttributeProgrammaticStreamSerialization;
    attrs[0].val.programmaticStreamSerializationAllowed = 1;
    cfg.attrs = attrs;
    cfg.numAttrs = 1;
    cudaLaunchKernelEx(&cfg, pool_kernel, (const float4*)video, out);
}